// round 13
// baseline (speedup 1.0000x reference)
#include <cuda_runtime.h>
#include <cstdint>

#define FULL 0xffffffffu
typedef unsigned long long ull;

__device__ float g_step;

// ---------- f32x2 packed helpers (sm_103a) ----------
static __device__ __forceinline__ ull pack2(float lo, float hi) {
    ull r;
    asm("mov.b64 %0, {%1, %2};" : "=l"(r) : "f"(lo), "f"(hi));
    return r;
}
static __device__ __forceinline__ void unpack2(ull v, float& lo, float& hi) {
    asm("mov.b64 {%0, %1}, %2;" : "=f"(lo), "=f"(hi) : "l"(v));
}
static __device__ __forceinline__ ull fma2(ull a, ull b, ull c) {
    ull d;
    asm("fma.rn.f32x2 %0, %1, %2, %3;" : "=l"(d) : "l"(a), "l"(b), "l"(c));
    return d;
}
static __device__ __forceinline__ ull add2(ull a, ull b) {
    ull d;
    asm("add.rn.f32x2 %0, %1, %2;" : "=l"(d) : "l"(a), "l"(b));
    return d;
}
static __device__ __forceinline__ float hadd2(ull v) {
    float lo, hi;
    unpack2(v, lo, hi);
    return lo + hi;
}

// ---------- power iteration body (1 warp): step = 1/(1.02 * lambda_max) ----------
static __device__ void power_body(const float* __restrict__ sigma, int lane) {
    __shared__ float vbuf[2][64];
    int c0 = 2 * lane;

    ull sp0[32], sp1[32];
    {
        const ull* r0 = reinterpret_cast<const ull*>(sigma + (size_t)c0 * 64);
        const ull* r1 = reinterpret_cast<const ull*>(sigma + (size_t)(c0 + 1) * 64);
        #pragma unroll
        for (int k = 0; k < 32; ++k) { sp0[k] = r0[k]; sp1[k] = r1[k]; }
    }

    float v0 = 0.125f, v1 = 0.125f;

    #pragma unroll 1
    for (int it = 0; it < 161; ++it) {
        int bsel = it & 1;
        *reinterpret_cast<ull*>(&vbuf[bsel][c0]) = pack2(v0, v1);
        __syncwarp();
        const ulonglong2* Y = reinterpret_cast<const ulonglong2*>(&vbuf[bsel][0]);
        ull a0 = 0ull, a1 = 0ull, b0 = 0ull, b1 = 0ull;
        #pragma unroll
        for (int q = 0; q < 16; ++q) {
            ulonglong2 yq = Y[q];
            a0 = fma2(sp0[2 * q],     yq.x, a0);
            a1 = fma2(sp1[2 * q],     yq.x, a1);
            b0 = fma2(sp0[2 * q + 1], yq.y, b0);
            b1 = fma2(sp1[2 * q + 1], yq.y, b1);
        }
        float u0 = hadd2(add2(a0, b0));
        float u1 = hadd2(add2(a1, b1));
        if (it == 160) {
            // Scale-invariant Rayleigh quotient: lam = (v.Sv)/(v.v)
            float num = u0 * v0 + u1 * v1;
            float den = v0 * v0 + v1 * v1;
            #pragma unroll
            for (int off = 16; off; off >>= 1) {
                num += __shfl_xor_sync(FULL, num, off);
                den += __shfl_xor_sync(FULL, den, off);
            }
            // 2% deflation guards a slight lambda underestimate; the converged
            // FISTA fixed point is step-independent.
            if (lane == 0) g_step = den / (1.02f * num);
            return;
        }
        if ((it & 15) == 15) {  // normalize every 16 iters (4^16 growth fits fp32)
            float nn = u0 * u0 + u1 * u1;
            #pragma unroll
            for (int off = 16; off; off >>= 1) nn += __shfl_xor_sync(FULL, nn, off);
            float inv = rsqrtf(nn);
            v0 = u0 * inv; v1 = u1 * inv;
        } else {
            v0 = u0; v1 = u1;
        }
    }
}

// ---------- Kernel 1: MLP -> mu, power iteration riding in the last block ----------
__global__ void __launch_bounds__(256) prep_kernel(
    const float* __restrict__ x,
    const float* __restrict__ W1, const float* __restrict__ b1,
    const float* __restrict__ W2, const float* __restrict__ b2,
    const float* __restrict__ W3, const float* __restrict__ b3,
    const float* __restrict__ sigma,
    float* __restrict__ mu_out, int B)
{
    if (blockIdx.x == gridDim.x - 1) {
        if (threadIdx.x < 32) power_body(sigma, threadIdx.x);
        return;
    }

    __shared__ float W1s[128 * 32];
    __shared__ float W2s[32 * 16];
    __shared__ float W3s[16 * 64];
    __shared__ float b1s[32], b2s[16], b3s[64];

    int tid = threadIdx.x;
    for (int i = tid; i < 4096; i += 256) W1s[i] = W1[i];
    for (int i = tid; i < 512;  i += 256) W2s[i] = W2[i];
    for (int i = tid; i < 1024; i += 256) W3s[i] = W3[i];
    if (tid < 32) b1s[tid] = b1[tid];
    if (tid < 16) b2s[tid] = b2[tid];
    if (tid < 64) b3s[tid] = b3[tid];
    __syncthreads();

    int lane = tid & 31;
    int row  = blockIdx.x * 8 + (tid >> 5);
    if (row >= B) return;

    float4 xv = reinterpret_cast<const float4*>(x + (size_t)row * 128)[lane];

    float h1 = b1s[lane];
    #pragma unroll
    for (int k = 0; k < 32; ++k) {
        float a0 = __shfl_sync(FULL, xv.x, k);
        float a1 = __shfl_sync(FULL, xv.y, k);
        float a2 = __shfl_sync(FULL, xv.z, k);
        float a3 = __shfl_sync(FULL, xv.w, k);
        int d = 4 * k;
        h1 = fmaf(a0, W1s[(d + 0) * 32 + lane], h1);
        h1 = fmaf(a1, W1s[(d + 1) * 32 + lane], h1);
        h1 = fmaf(a2, W1s[(d + 2) * 32 + lane], h1);
        h1 = fmaf(a3, W1s[(d + 3) * 32 + lane], h1);
    }
    h1 = fmaxf(h1, 0.f);

    int j = lane & 15;
    float h2 = b2s[j];
    #pragma unroll
    for (int k = 0; k < 32; ++k) {
        float hk = __shfl_sync(FULL, h1, k);
        h2 = fmaf(hk, W2s[k * 16 + j], h2);
    }
    h2 = fmaxf(h2, 0.f);

    float m0 = b3s[2 * lane];
    float m1 = b3s[2 * lane + 1];
    #pragma unroll
    for (int k = 0; k < 16; ++k) {
        float hk = __shfl_sync(FULL, h2, k);
        m0 = fmaf(hk, W3s[k * 64 + 2 * lane],     m0);
        m1 = fmaf(hk, W3s[k * 64 + 2 * lane + 1], m1);
    }
    reinterpret_cast<float2*>(mu_out + (size_t)row * 64)[lane] = make_float2(m0, m1);
}

// ---------- Kernel 2: FISTA + per-row adaptive restart, 2 rows/warp ----------
#define FIX    2097152.0f          /* 2^21 fixed-point scale for REDUX float sums */
#define INVFIX (1.0f / 2097152.0f)
#define FIXR   16777216.0f         /* 2^24 scale for the restart sign test */
#define NROW 2

__global__ void __launch_bounds__(128, 3) fista_kernel(
    const float* __restrict__ sigma,
    const float* __restrict__ gamma,
    float* __restrict__ out, int B)
{
    __shared__ float ybuf[2][4][NROW][64];   // [buf][warp][row][64] = 4KB

    int warp = threadIdx.x >> 5;
    int lane = threadIdx.x & 31;
    int gw   = blockIdx.x * 4 + warp;        // warp task id (NROW rows each)
    int row0 = NROW * gw;
    if (row0 >= B) return;

    const float gm   = __ldg(gamma);
    const float step = g_step;
    const int   c0   = 2 * lane;             // lane owns columns 2l, 2l+1

    ull sp0[32], sp1[32];
    {
        const ull* r0 = reinterpret_cast<const ull*>(sigma + (size_t)c0 * 64);
        const ull* r1 = reinterpret_cast<const ull*>(sigma + (size_t)(c0 + 1) * 64);
        #pragma unroll
        for (int k = 0; k < 32; ++k) { sp0[k] = r0[k]; sp1[k] = r1[k]; }
    }

    // p = -gamma * mu  (mu at out[B*64 + ...], written by prep_kernel)
    float p0[NROW], p1[NROW];
    #pragma unroll
    for (int r = 0; r < NROW; ++r) {
        const float2 m = reinterpret_cast<const float2*>(
            out + (size_t)B * 64 + (size_t)(row0 + r) * 64)[lane];
        p0[r] = -gm * m.x; p1[r] = -gm * m.y;
    }

    float w0[NROW], w1[NROW], y0[NROW], y1[NROW], th[NROW], tr[NROW];
    #pragma unroll
    for (int r = 0; r < NROW; ++r) {
        w0[r] = 1.f / 64.f; w1[r] = 1.f / 64.f;
        y0[r] = w0[r];      y1[r] = w1[r];
        th[r] = -1e30f;     // warm-start theta; -inf => cold start on iter 0
        tr[r] = 1.f;        // per-row momentum parameter
    }
    int cc = 0;

    #pragma unroll 1
    for (int it = 0; it < 200; ++it) {
        int bsel = it & 1;
        #pragma unroll
        for (int r = 0; r < NROW; ++r)
            *reinterpret_cast<ull*>(&ybuf[bsel][warp][r][c0]) = pack2(y0[r], y1[r]);
        __syncwarp();

        // grad = y @ Sigma + p  (Sigma symmetric; broadcast LDS.128 reads)
        ull a0[NROW], a1[NROW];
        #pragma unroll
        for (int r = 0; r < NROW; ++r) { a0[r] = 0ull; a1[r] = 0ull; }
        #pragma unroll
        for (int q = 0; q < 16; ++q) {
            #pragma unroll
            for (int r = 0; r < NROW; ++r) {
                ulonglong2 yq = reinterpret_cast<const ulonglong2*>(&ybuf[bsel][warp][r][0])[q];
                a0[r] = fma2(sp0[2 * q],     yq.x, a0[r]);
                a1[r] = fma2(sp1[2 * q],     yq.x, a1[r]);
                a0[r] = fma2(sp0[2 * q + 1], yq.y, a0[r]);
                a1[r] = fma2(sp1[2 * q + 1], yq.y, a1[r]);
            }
        }

        float v0[NROW], v1[NROW];
        #pragma unroll
        for (int r = 0; r < NROW; ++r) {
            float gr0 = hadd2(a0[r]) + p0[r];
            float gr1 = hadd2(a1[r]) + p1[r];
            v0[r] = fmaf(-step, gr0, y0[r]);
            v1[r] = fmaf(-step, gr1, y1[r]);
        }

        // Simplex projection: warm-started Newton on g(th)=sum(max(v-th,0))-1.
        // First step lands <= th*, then monotone increase, exact finite stop.
        // Sum via 2^21 fixed-point REDUX (theta err ~1e-6 << 1e-3 budget);
        // active-set count via ballot+popc (VOTE pipe, off the REDUX chain).
        int kc[NROW];
        #pragma unroll
        for (int r = 0; r < NROW; ++r) kc[r] = -1;

        #pragma unroll 1
        for (int pass = 0; pass < 64; ++pass) {
            int s[NROW], c[NROW];
            #pragma unroll
            for (int r = 0; r < NROW; ++r) {
                bool g0 = v0[r] > th[r], g1 = v1[r] > th[r];
                float ps = (g0 ? v0[r] : 0.f) + (g1 ? v1[r] : 0.f);
                s[r] = __reduce_add_sync(FULL, __float2int_rn(ps * FIX));
                c[r] = __popc(__ballot_sync(FULL, g0)) + __popc(__ballot_sync(FULL, g1));
            }
            bool done = true;
            #pragma unroll
            for (int r = 0; r < NROW; ++r) {
                done &= (c[r] == kc[r]);
                kc[r] = c[r];
                // c==0 only possible on pass 0 (warm theta too high): cold restart
                th[r] = (c[r] > 0)
                    ? __fdividef((float)s[r] * INVFIX - 1.f, (float)c[r])
                    : -1e30f;
            }
            if (done) break;  // same active set twice => consistent fixed point
        }

        float mxchg = 0.f;
        float wn0[NROW], wn1[NROW];
        #pragma unroll
        for (int r = 0; r < NROW; ++r) {
            wn0[r] = fmaxf(v0[r] - th[r], 0.f);
            wn1[r] = fmaxf(v1[r] - th[r], 0.f);
            mxchg = fmaxf(mxchg, fmaxf(fabsf(wn0[r] - w0[r]), fabsf(wn1[r] - w1[r])));
        }

        // Per-row adaptive restart (O'Donoghue-Candes): dump momentum when
        // <y - w_new, w_new - w_old> > 0. Decision only affects SPEED, never
        // the fixed point, so a clamped fixed-point sign test is safe.
        #pragma unroll
        for (int r = 0; r < NROW; ++r) {
            float dot = (y0[r] - wn0[r]) * (wn0[r] - w0[r])
                      + (y1[r] - wn1[r]) * (wn1[r] - w1[r]);
            dot = fminf(fmaxf(dot, -1.f), 1.f);
            int sd = __reduce_add_sync(FULL, __float2int_rn(dot * FIXR));
            bool restart = sd > 0;
            float tn = restart ? 1.f
                               : 0.5f * (1.f + sqrtf(fmaf(4.f * tr[r], tr[r], 1.f)));
            float cf = restart ? 0.f : __fdividef(tr[r] - 1.f, tn);
            y0[r] = fmaf(cf, wn0[r] - w0[r], wn0[r]);
            y1[r] = fmaf(cf, wn1[r] - w1[r], wn1[r]);
            w0[r] = wn0[r]; w1[r] = wn1[r];
            tr[r] = tn;
        }

        // Early exit: w frozen (<1e-7) across whole warp for 2 consecutive iters.
        if (__all_sync(FULL, mxchg < 1e-7f)) {
            if (++cc >= 2) break;
        } else {
            cc = 0;
        }
    }

    #pragma unroll
    for (int r = 0; r < NROW; ++r)
        reinterpret_cast<float2*>(out + (size_t)(row0 + r) * 64)[lane] =
            make_float2(w0[r], w1[r]);
}

// ---------- launch ----------
extern "C" void kernel_launch(void* const* d_in, const int* in_sizes, int n_in,
                              void* d_out, int out_size) {
    const float* x     = (const float*)d_in[0];
    const float* W1    = (const float*)d_in[1];
    const float* b1    = (const float*)d_in[2];
    const float* W2    = (const float*)d_in[3];
    const float* b2    = (const float*)d_in[4];
    const float* W3    = (const float*)d_in[5];
    const float* b3    = (const float*)d_in[6];
    const float* sigma = (const float*)d_in[7];
    const float* gamma = (const float*)d_in[8];
    float* out = (float*)d_out;

    int B = in_sizes[0] / 128;  // x is [B, 128]

    int mlp_blocks = (B + 7) / 8;
    prep_kernel<<<mlp_blocks + 1, 256>>>(x, W1, b1, W2, b2, W3, b3, sigma,
                                         out + (size_t)B * 64, B);
    int warps = (B + NROW - 1) / NROW;
    fista_kernel<<<(warps + 3) / 4, 128>>>(sigma, gamma, out, B);
}

// round 15
// speedup vs baseline: 1.4634x; 1.4634x over previous
#include <cuda_runtime.h>
#include <cstdint>

#define FULL 0xffffffffu
typedef unsigned long long ull;

__device__ float g_step;

// ---------- f32x2 packed helpers (sm_103a) ----------
static __device__ __forceinline__ ull pack2(float lo, float hi) {
    ull r;
    asm("mov.b64 %0, {%1, %2};" : "=l"(r) : "f"(lo), "f"(hi));
    return r;
}
static __device__ __forceinline__ void unpack2(ull v, float& lo, float& hi) {
    asm("mov.b64 {%0, %1}, %2;" : "=f"(lo), "=f"(hi) : "l"(v));
}
static __device__ __forceinline__ ull fma2(ull a, ull b, ull c) {
    ull d;
    asm("fma.rn.f32x2 %0, %1, %2, %3;" : "=l"(d) : "l"(a), "l"(b), "l"(c));
    return d;
}
static __device__ __forceinline__ ull add2(ull a, ull b) {
    ull d;
    asm("add.rn.f32x2 %0, %1, %2;" : "=l"(d) : "l"(a), "l"(b));
    return d;
}
static __device__ __forceinline__ float hadd2(ull v) {
    float lo, hi;
    unpack2(v, lo, hi);
    return lo + hi;
}

// ---------- power iteration body (1 warp): step = 1/(1.02 * lambda_max) ----------
static __device__ void power_body(const float* __restrict__ sigma, int lane) {
    __shared__ float vbuf[2][64];
    int c0 = 2 * lane;

    ull sp0[32], sp1[32];
    {
        const ull* r0 = reinterpret_cast<const ull*>(sigma + (size_t)c0 * 64);
        const ull* r1 = reinterpret_cast<const ull*>(sigma + (size_t)(c0 + 1) * 64);
        #pragma unroll
        for (int k = 0; k < 32; ++k) { sp0[k] = r0[k]; sp1[k] = r1[k]; }
    }

    float v0 = 0.125f, v1 = 0.125f;

    #pragma unroll 1
    for (int it = 0; it < 161; ++it) {
        int bsel = it & 1;
        *reinterpret_cast<ull*>(&vbuf[bsel][c0]) = pack2(v0, v1);
        __syncwarp();
        const ulonglong2* Y = reinterpret_cast<const ulonglong2*>(&vbuf[bsel][0]);
        ull a0 = 0ull, a1 = 0ull, b0 = 0ull, b1 = 0ull;
        #pragma unroll
        for (int q = 0; q < 16; ++q) {
            ulonglong2 yq = Y[q];
            a0 = fma2(sp0[2 * q],     yq.x, a0);
            a1 = fma2(sp1[2 * q],     yq.x, a1);
            b0 = fma2(sp0[2 * q + 1], yq.y, b0);
            b1 = fma2(sp1[2 * q + 1], yq.y, b1);
        }
        float u0 = hadd2(add2(a0, b0));
        float u1 = hadd2(add2(a1, b1));
        if (it == 160) {
            // Scale-invariant Rayleigh quotient: lam = (v.Sv)/(v.v)
            float num = u0 * v0 + u1 * v1;
            float den = v0 * v0 + v1 * v1;
            #pragma unroll
            for (int off = 16; off; off >>= 1) {
                num += __shfl_xor_sync(FULL, num, off);
                den += __shfl_xor_sync(FULL, den, off);
            }
            // 2% deflation guards a slight lambda underestimate; the converged
            // FISTA fixed point is step-independent.
            if (lane == 0) g_step = den / (1.02f * num);
            return;
        }
        if ((it & 15) == 15) {  // normalize every 16 iters (4^16 growth fits fp32)
            float nn = u0 * u0 + u1 * u1;
            #pragma unroll
            for (int off = 16; off; off >>= 1) nn += __shfl_xor_sync(FULL, nn, off);
            float inv = rsqrtf(nn);
            v0 = u0 * inv; v1 = u1 * inv;
        } else {
            v0 = u0; v1 = u1;
        }
    }
}

// ---------- Kernel 1: MLP -> mu, power iteration riding in the last block ----------
__global__ void __launch_bounds__(256) prep_kernel(
    const float* __restrict__ x,
    const float* __restrict__ W1, const float* __restrict__ b1,
    const float* __restrict__ W2, const float* __restrict__ b2,
    const float* __restrict__ W3, const float* __restrict__ b3,
    const float* __restrict__ sigma,
    float* __restrict__ mu_out, int B)
{
    if (blockIdx.x == gridDim.x - 1) {
        if (threadIdx.x < 32) power_body(sigma, threadIdx.x);
        return;
    }

    __shared__ float W1s[128 * 32];
    __shared__ float W2s[32 * 16];
    __shared__ float W3s[16 * 64];
    __shared__ float b1s[32], b2s[16], b3s[64];

    int tid = threadIdx.x;
    for (int i = tid; i < 4096; i += 256) W1s[i] = W1[i];
    for (int i = tid; i < 512;  i += 256) W2s[i] = W2[i];
    for (int i = tid; i < 1024; i += 256) W3s[i] = W3[i];
    if (tid < 32) b1s[tid] = b1[tid];
    if (tid < 16) b2s[tid] = b2[tid];
    if (tid < 64) b3s[tid] = b3[tid];
    __syncthreads();

    int lane = tid & 31;
    int row  = blockIdx.x * 8 + (tid >> 5);
    if (row >= B) return;

    float4 xv = reinterpret_cast<const float4*>(x + (size_t)row * 128)[lane];

    float h1 = b1s[lane];
    #pragma unroll
    for (int k = 0; k < 32; ++k) {
        float a0 = __shfl_sync(FULL, xv.x, k);
        float a1 = __shfl_sync(FULL, xv.y, k);
        float a2 = __shfl_sync(FULL, xv.z, k);
        float a3 = __shfl_sync(FULL, xv.w, k);
        int d = 4 * k;
        h1 = fmaf(a0, W1s[(d + 0) * 32 + lane], h1);
        h1 = fmaf(a1, W1s[(d + 1) * 32 + lane], h1);
        h1 = fmaf(a2, W1s[(d + 2) * 32 + lane], h1);
        h1 = fmaf(a3, W1s[(d + 3) * 32 + lane], h1);
    }
    h1 = fmaxf(h1, 0.f);

    int j = lane & 15;
    float h2 = b2s[j];
    #pragma unroll
    for (int k = 0; k < 32; ++k) {
        float hk = __shfl_sync(FULL, h1, k);
        h2 = fmaf(hk, W2s[k * 16 + j], h2);
    }
    h2 = fmaxf(h2, 0.f);

    float m0 = b3s[2 * lane];
    float m1 = b3s[2 * lane + 1];
    #pragma unroll
    for (int k = 0; k < 16; ++k) {
        float hk = __shfl_sync(FULL, h2, k);
        m0 = fmaf(hk, W3s[k * 64 + 2 * lane],     m0);
        m1 = fmaf(hk, W3s[k * 64 + 2 * lane + 1], m1);
    }
    reinterpret_cast<float2*>(mu_out + (size_t)row * 64)[lane] = make_float2(m0, m1);
}

// ---------- Kernel 2: FISTA, fixed-period restart, 2 rows/warp ----------
#define FIX    2097152.0f          /* 2^21 fixed-point scale for REDUX float sums */
#define INVFIX (1.0f / 2097152.0f)
#define NROW 2
#define RESTART 32                 /* ~e*sqrt(kappa_eff); kills FISTA ripple */

__global__ void __launch_bounds__(128, 3) fista_kernel(
    const float* __restrict__ sigma,
    const float* __restrict__ gamma,
    float* __restrict__ out, int B)
{
    __shared__ float ybuf[2][4][NROW][64];   // [buf][warp][row][64] = 4KB

    int warp = threadIdx.x >> 5;
    int lane = threadIdx.x & 31;
    int gw   = blockIdx.x * 4 + warp;        // warp task id (NROW rows each)
    int row0 = NROW * gw;
    if (row0 >= B) return;

    const float gm   = __ldg(gamma);
    const float step = g_step;
    const int   c0   = 2 * lane;             // lane owns columns 2l, 2l+1

    ull sp0[32], sp1[32];
    {
        const ull* r0 = reinterpret_cast<const ull*>(sigma + (size_t)c0 * 64);
        const ull* r1 = reinterpret_cast<const ull*>(sigma + (size_t)(c0 + 1) * 64);
        #pragma unroll
        for (int k = 0; k < 32; ++k) { sp0[k] = r0[k]; sp1[k] = r1[k]; }
    }

    // p = -gamma * mu  (mu at out[B*64 + ...], written by prep_kernel)
    float p0[NROW], p1[NROW];
    #pragma unroll
    for (int r = 0; r < NROW; ++r) {
        const float2 m = reinterpret_cast<const float2*>(
            out + (size_t)B * 64 + (size_t)(row0 + r) * 64)[lane];
        p0[r] = -gm * m.x; p1[r] = -gm * m.y;
    }

    float w0[NROW], w1[NROW], y0[NROW], y1[NROW], th[NROW];
    #pragma unroll
    for (int r = 0; r < NROW; ++r) {
        w0[r] = 1.f / 64.f; w1[r] = 1.f / 64.f;
        y0[r] = w0[r];      y1[r] = w1[r];
        th[r] = -1e30f;     // warm-start theta; -inf => cold start on iter 0
    }
    float t = 1.f;
    int rsc = 0;

    #pragma unroll 1
    for (int it = 0; it < 200; ++it) {
        int bsel = it & 1;
        #pragma unroll
        for (int r = 0; r < NROW; ++r)
            *reinterpret_cast<ull*>(&ybuf[bsel][warp][r][c0]) = pack2(y0[r], y1[r]);
        __syncwarp();

        // grad = y @ Sigma + p  (Sigma symmetric; broadcast LDS.128 reads)
        ull a0[NROW], a1[NROW];
        #pragma unroll
        for (int r = 0; r < NROW; ++r) { a0[r] = 0ull; a1[r] = 0ull; }
        #pragma unroll
        for (int q = 0; q < 16; ++q) {
            #pragma unroll
            for (int r = 0; r < NROW; ++r) {
                ulonglong2 yq = reinterpret_cast<const ulonglong2*>(&ybuf[bsel][warp][r][0])[q];
                a0[r] = fma2(sp0[2 * q],     yq.x, a0[r]);
                a1[r] = fma2(sp1[2 * q],     yq.x, a1[r]);
                a0[r] = fma2(sp0[2 * q + 1], yq.y, a0[r]);
                a1[r] = fma2(sp1[2 * q + 1], yq.y, a1[r]);
            }
        }

        float v0[NROW], v1[NROW];
        #pragma unroll
        for (int r = 0; r < NROW; ++r) {
            float gr0 = hadd2(a0[r]) + p0[r];
            float gr1 = hadd2(a1[r]) + p1[r];
            v0[r] = fmaf(-step, gr0, y0[r]);
            v1[r] = fmaf(-step, gr1, y1[r]);
        }

        // Simplex projection: warm-started Newton on g(th)=sum(max(v-th,0))-1.
        // First step lands <= th*, then monotone increase, exact finite stop.
        // Sum via 2^21 fixed-point REDUX (theta err ~1e-6 << 1e-3 budget);
        // active-set count via ballot+popc (VOTE pipe, off the REDUX chain).
        int kc[NROW];
        #pragma unroll
        for (int r = 0; r < NROW; ++r) kc[r] = -1;

        #pragma unroll 1
        for (int pass = 0; pass < 64; ++pass) {
            int s[NROW], c[NROW];
            #pragma unroll
            for (int r = 0; r < NROW; ++r) {
                bool g0 = v0[r] > th[r], g1 = v1[r] > th[r];
                float ps = (g0 ? v0[r] : 0.f) + (g1 ? v1[r] : 0.f);
                s[r] = __reduce_add_sync(FULL, __float2int_rn(ps * FIX));
                c[r] = __popc(__ballot_sync(FULL, g0)) + __popc(__ballot_sync(FULL, g1));
            }
            bool done = true;
            #pragma unroll
            for (int r = 0; r < NROW; ++r) {
                done &= (c[r] == kc[r]);
                kc[r] = c[r];
                // c==0 only possible on pass 0 (warm theta too high): cold restart
                th[r] = (c[r] > 0)
                    ? __fdividef((float)s[r] * INVFIX - 1.f, (float)c[r])
                    : -1e30f;
            }
            if (done) break;  // same active set twice => consistent fixed point
        }

        float mxchg = 0.f;
        float wn0[NROW], wn1[NROW];
        #pragma unroll
        for (int r = 0; r < NROW; ++r) {
            wn0[r] = fmaxf(v0[r] - th[r], 0.f);
            wn1[r] = fmaxf(v1[r] - th[r], 0.f);
            mxchg = fmaxf(mxchg, fmaxf(fabsf(wn0[r] - w0[r]), fabsf(wn1[r] - w1[r])));
        }

        // Fixed-period restart: dump momentum so w converges monotonically
        // (same fixed point; lets the early exit below fire early).
        bool restart = (++rsc == RESTART);
        if (restart) rsc = 0;
        float tn = restart ? 1.f : 0.5f * (1.f + sqrtf(fmaf(4.f * t, t, 1.f)));
        float cf = restart ? 0.f : __fdividef(t - 1.f, tn);
        #pragma unroll
        for (int r = 0; r < NROW; ++r) {
            y0[r] = fmaf(cf, wn0[r] - w0[r], wn0[r]);
            y1[r] = fmaf(cf, wn1[r] - w1[r], wn1[r]);
            w0[r] = wn0[r]; w1[r] = wn1[r];
        }
        t = tn;

        // Early exit: whole warp's w frozen (<1e-7) for one iteration.
        // Under restarted (monotone) convergence this means fully converged.
        if (__all_sync(FULL, mxchg < 1e-7f)) break;
    }

    #pragma unroll
    for (int r = 0; r < NROW; ++r)
        reinterpret_cast<float2*>(out + (size_t)(row0 + r) * 64)[lane] =
            make_float2(w0[r], w1[r]);
}

// ---------- launch ----------
extern "C" void kernel_launch(void* const* d_in, const int* in_sizes, int n_in,
                              void* d_out, int out_size) {
    const float* x     = (const float*)d_in[0];
    const float* W1    = (const float*)d_in[1];
    const float* b1    = (const float*)d_in[2];
    const float* W2    = (const float*)d_in[3];
    const float* b2    = (const float*)d_in[4];
    const float* W3    = (const float*)d_in[5];
    const float* b3    = (const float*)d_in[6];
    const float* sigma = (const float*)d_in[7];
    const float* gamma = (const float*)d_in[8];
    float* out = (float*)d_out;

    int B = in_sizes[0] / 128;  // x is [B, 128]

    int mlp_blocks = (B + 7) / 8;
    prep_kernel<<<mlp_blocks + 1, 256>>>(x, W1, b1, W2, b2, W3, b3, sigma,
                                         out + (size_t)B * 64, B);
    int warps = (B + NROW - 1) / NROW;
    fista_kernel<<<(warps + 3) / 4, 128>>>(sigma, gamma, out, B);
}

// round 16
// speedup vs baseline: 2.2722x; 1.5527x over previous
#include <cuda_runtime.h>
#include <cstdint>

#define FULL 0xffffffffu
typedef unsigned long long ull;

__device__ float g_step;

// ---------- f32x2 packed helpers (sm_103a) ----------
static __device__ __forceinline__ ull pack2(float lo, float hi) {
    ull r;
    asm("mov.b64 %0, {%1, %2};" : "=l"(r) : "f"(lo), "f"(hi));
    return r;
}
static __device__ __forceinline__ void unpack2(ull v, float& lo, float& hi) {
    asm("mov.b64 {%0, %1}, %2;" : "=f"(lo), "=f"(hi) : "l"(v));
}
static __device__ __forceinline__ ull fma2(ull a, ull b, ull c) {
    ull d;
    asm("fma.rn.f32x2 %0, %1, %2, %3;" : "=l"(d) : "l"(a), "l"(b), "l"(c));
    return d;
}
static __device__ __forceinline__ ull add2(ull a, ull b) {
    ull d;
    asm("add.rn.f32x2 %0, %1, %2;" : "=l"(d) : "l"(a), "l"(b));
    return d;
}
static __device__ __forceinline__ float hadd2(ull v) {
    float lo, hi;
    unpack2(v, lo, hi);
    return lo + hi;
}

// ---------- power iteration body (1 warp): step = 1/(1.02 * lambda_max) ----------
static __device__ void power_body(const float* __restrict__ sigma, int lane) {
    __shared__ float vbuf[2][64];
    int c0 = 2 * lane;

    ull sp0[32], sp1[32];
    {
        const ull* r0 = reinterpret_cast<const ull*>(sigma + (size_t)c0 * 64);
        const ull* r1 = reinterpret_cast<const ull*>(sigma + (size_t)(c0 + 1) * 64);
        #pragma unroll
        for (int k = 0; k < 32; ++k) { sp0[k] = r0[k]; sp1[k] = r1[k]; }
    }

    float v0 = 0.125f, v1 = 0.125f;

    // 81 iters: Rayleigh err ~ (lam2/lam1)^162 << the 2% deflation guard below.
    #pragma unroll 1
    for (int it = 0; it < 81; ++it) {
        int bsel = it & 1;
        *reinterpret_cast<ull*>(&vbuf[bsel][c0]) = pack2(v0, v1);
        __syncwarp();
        const ulonglong2* Y = reinterpret_cast<const ulonglong2*>(&vbuf[bsel][0]);
        ull a0 = 0ull, a1 = 0ull, b0 = 0ull, b1 = 0ull;
        #pragma unroll
        for (int q = 0; q < 16; ++q) {
            ulonglong2 yq = Y[q];
            a0 = fma2(sp0[2 * q],     yq.x, a0);
            a1 = fma2(sp1[2 * q],     yq.x, a1);
            b0 = fma2(sp0[2 * q + 1], yq.y, b0);
            b1 = fma2(sp1[2 * q + 1], yq.y, b1);
        }
        float u0 = hadd2(add2(a0, b0));
        float u1 = hadd2(add2(a1, b1));
        if (it == 80) {
            // Scale-invariant Rayleigh quotient: lam = (v.Sv)/(v.v)
            float num = u0 * v0 + u1 * v1;
            float den = v0 * v0 + v1 * v1;
            #pragma unroll
            for (int off = 16; off; off >>= 1) {
                num += __shfl_xor_sync(FULL, num, off);
                den += __shfl_xor_sync(FULL, den, off);
            }
            // 2% deflation guards a slight lambda underestimate; the converged
            // FISTA fixed point is step-independent.
            if (lane == 0) g_step = den / (1.02f * num);
            return;
        }
        if ((it & 15) == 15) {  // normalize every 16 iters (4^16 growth fits fp32)
            float nn = u0 * u0 + u1 * u1;
            #pragma unroll
            for (int off = 16; off; off >>= 1) nn += __shfl_xor_sync(FULL, nn, off);
            float inv = rsqrtf(nn);
            v0 = u0 * inv; v1 = u1 * inv;
        } else {
            v0 = u0; v1 = u1;
        }
    }
}

// ---------- Kernel 1: MLP -> mu, power iteration riding in the last block ----------
__global__ void __launch_bounds__(256) prep_kernel(
    const float* __restrict__ x,
    const float* __restrict__ W1, const float* __restrict__ b1,
    const float* __restrict__ W2, const float* __restrict__ b2,
    const float* __restrict__ W3, const float* __restrict__ b3,
    const float* __restrict__ sigma,
    float* __restrict__ mu_out, int B)
{
    if (blockIdx.x == gridDim.x - 1) {
        if (threadIdx.x < 32) power_body(sigma, threadIdx.x);
        return;
    }

    __shared__ float W1s[128 * 32];
    __shared__ float W2s[32 * 16];
    __shared__ float W3s[16 * 64];
    __shared__ float b1s[32], b2s[16], b3s[64];

    int tid = threadIdx.x;
    for (int i = tid; i < 4096; i += 256) W1s[i] = W1[i];
    for (int i = tid; i < 512;  i += 256) W2s[i] = W2[i];
    for (int i = tid; i < 1024; i += 256) W3s[i] = W3[i];
    if (tid < 32) b1s[tid] = b1[tid];
    if (tid < 16) b2s[tid] = b2[tid];
    if (tid < 64) b3s[tid] = b3[tid];
    __syncthreads();

    int lane = tid & 31;
    int row  = blockIdx.x * 8 + (tid >> 5);
    if (row >= B) return;

    float4 xv = reinterpret_cast<const float4*>(x + (size_t)row * 128)[lane];

    float h1 = b1s[lane];
    #pragma unroll
    for (int k = 0; k < 32; ++k) {
        float a0 = __shfl_sync(FULL, xv.x, k);
        float a1 = __shfl_sync(FULL, xv.y, k);
        float a2 = __shfl_sync(FULL, xv.z, k);
        float a3 = __shfl_sync(FULL, xv.w, k);
        int d = 4 * k;
        h1 = fmaf(a0, W1s[(d + 0) * 32 + lane], h1);
        h1 = fmaf(a1, W1s[(d + 1) * 32 + lane], h1);
        h1 = fmaf(a2, W1s[(d + 2) * 32 + lane], h1);
        h1 = fmaf(a3, W1s[(d + 3) * 32 + lane], h1);
    }
    h1 = fmaxf(h1, 0.f);

    int j = lane & 15;
    float h2 = b2s[j];
    #pragma unroll
    for (int k = 0; k < 32; ++k) {
        float hk = __shfl_sync(FULL, h1, k);
        h2 = fmaf(hk, W2s[k * 16 + j], h2);
    }
    h2 = fmaxf(h2, 0.f);

    float m0 = b3s[2 * lane];
    float m1 = b3s[2 * lane + 1];
    #pragma unroll
    for (int k = 0; k < 16; ++k) {
        float hk = __shfl_sync(FULL, h2, k);
        m0 = fmaf(hk, W3s[k * 64 + 2 * lane],     m0);
        m1 = fmaf(hk, W3s[k * 64 + 2 * lane + 1], m1);
    }
    reinterpret_cast<float2*>(mu_out + (size_t)row * 64)[lane] = make_float2(m0, m1);
}

// ---------- Kernel 2: FISTA, fixed-period restart, 2 rows/warp ----------
#define FIX    2097152.0f          /* 2^21 fixed-point scale for REDUX float sums */
#define INVFIX (1.0f / 2097152.0f)
#define NROW 2
#define RESTART 32                 /* ~e*sqrt(kappa_eff); kills FISTA ripple */

__global__ void __launch_bounds__(128, 3) fista_kernel(
    const float* __restrict__ sigma,
    const float* __restrict__ gamma,
    float* __restrict__ out, int B)
{
    __shared__ float ybuf[2][4][NROW][64];   // [buf][warp][row][64] = 4KB

    int warp = threadIdx.x >> 5;
    int lane = threadIdx.x & 31;
    int gw   = blockIdx.x * 4 + warp;        // warp task id (NROW rows each)
    int row0 = NROW * gw;
    if (row0 >= B) return;

    const float gm   = __ldg(gamma);
    const float step = g_step;
    const int   c0   = 2 * lane;             // lane owns columns 2l, 2l+1

    ull sp0[32], sp1[32];
    {
        const ull* r0 = reinterpret_cast<const ull*>(sigma + (size_t)c0 * 64);
        const ull* r1 = reinterpret_cast<const ull*>(sigma + (size_t)(c0 + 1) * 64);
        #pragma unroll
        for (int k = 0; k < 32; ++k) { sp0[k] = r0[k]; sp1[k] = r1[k]; }
    }

    // p = -gamma * mu  (mu at out[B*64 + ...], written by prep_kernel)
    float p0[NROW], p1[NROW];
    #pragma unroll
    for (int r = 0; r < NROW; ++r) {
        const float2 m = reinterpret_cast<const float2*>(
            out + (size_t)B * 64 + (size_t)(row0 + r) * 64)[lane];
        p0[r] = -gm * m.x; p1[r] = -gm * m.y;
    }

    float w0[NROW], w1[NROW], y0[NROW], y1[NROW], th[NROW];
    #pragma unroll
    for (int r = 0; r < NROW; ++r) {
        w0[r] = 1.f / 64.f; w1[r] = 1.f / 64.f;
        y0[r] = w0[r];      y1[r] = w1[r];
        th[r] = -1e30f;     // warm-start theta; -inf => cold start on iter 0
    }
    float t = 1.f;
    int rsc = 0;

    #pragma unroll 1
    for (int it = 0; it < 200; ++it) {
        int bsel = it & 1;
        #pragma unroll
        for (int r = 0; r < NROW; ++r)
            *reinterpret_cast<ull*>(&ybuf[bsel][warp][r][c0]) = pack2(y0[r], y1[r]);
        __syncwarp();

        // grad = y @ Sigma + p  (Sigma symmetric; broadcast LDS.128 reads)
        ull a0[NROW], a1[NROW];
        #pragma unroll
        for (int r = 0; r < NROW; ++r) { a0[r] = 0ull; a1[r] = 0ull; }
        #pragma unroll
        for (int q = 0; q < 16; ++q) {
            #pragma unroll
            for (int r = 0; r < NROW; ++r) {
                ulonglong2 yq = reinterpret_cast<const ulonglong2*>(&ybuf[bsel][warp][r][0])[q];
                a0[r] = fma2(sp0[2 * q],     yq.x, a0[r]);
                a1[r] = fma2(sp1[2 * q],     yq.x, a1[r]);
                a0[r] = fma2(sp0[2 * q + 1], yq.y, a0[r]);
                a1[r] = fma2(sp1[2 * q + 1], yq.y, a1[r]);
            }
        }

        float v0[NROW], v1[NROW];
        #pragma unroll
        for (int r = 0; r < NROW; ++r) {
            float gr0 = hadd2(a0[r]) + p0[r];
            float gr1 = hadd2(a1[r]) + p1[r];
            v0[r] = fmaf(-step, gr0, y0[r]);
            v1[r] = fmaf(-step, gr1, y1[r]);
        }

        // Simplex projection: warm-started Newton on g(th)=sum(max(v-th,0))-1,
        // with EXACT active-set tracking via ballot masks. Steady state
        // (set unchanged since last iter) costs 1 REDUX + 1 div + 4 ballots.
        // Sum via 2^21 fixed-point REDUX (theta err ~1e-6 << 1e-3 budget).
        bool g0[NROW], g1[NROW];
        unsigned m0[NROW], m1[NROW];
        #pragma unroll
        for (int r = 0; r < NROW; ++r) {
            g0[r] = v0[r] > th[r];
            g1[r] = v1[r] > th[r];
            m0[r] = __ballot_sync(FULL, g0[r]);
            m1[r] = __ballot_sync(FULL, g1[r]);
        }

        #pragma unroll 1
        for (int pass = 0; pass < 64; ++pass) {
            #pragma unroll
            for (int r = 0; r < NROW; ++r) {
                int c = __popc(m0[r]) + __popc(m1[r]);
                float ps = (g0[r] ? v0[r] : 0.f) + (g1[r] ? v1[r] : 0.f);
                int s = __reduce_add_sync(FULL, __float2int_rn(ps * FIX));
                // c==0 only possible on pass 0 (warm theta too high): cold restart
                th[r] = (c > 0)
                    ? __fdividef((float)s * INVFIX - 1.f, (float)c)
                    : -1e30f;
            }
            bool done = true;
            #pragma unroll
            for (int r = 0; r < NROW; ++r) {
                bool n0 = v0[r] > th[r], n1 = v1[r] > th[r];
                unsigned nm0 = __ballot_sync(FULL, n0);
                unsigned nm1 = __ballot_sync(FULL, n1);
                done &= (nm0 == m0[r]) & (nm1 == m1[r]);
                g0[r] = n0; g1[r] = n1; m0[r] = nm0; m1[r] = nm1;
            }
            if (done) break;  // active set fixed point => theta exact
        }

        float mxchg = 0.f;
        float wn0[NROW], wn1[NROW];
        #pragma unroll
        for (int r = 0; r < NROW; ++r) {
            wn0[r] = fmaxf(v0[r] - th[r], 0.f);
            wn1[r] = fmaxf(v1[r] - th[r], 0.f);
            mxchg = fmaxf(mxchg, fmaxf(fabsf(wn0[r] - w0[r]), fabsf(wn1[r] - w1[r])));
        }

        // Fixed-period restart: dump momentum so w converges monotonically
        // (same fixed point; lets the early exit below fire early).
        bool restart = (++rsc == RESTART);
        if (restart) rsc = 0;
        float tn = restart ? 1.f : 0.5f * (1.f + sqrtf(fmaf(4.f * t, t, 1.f)));
        float cf = restart ? 0.f : __fdividef(t - 1.f, tn);
        #pragma unroll
        for (int r = 0; r < NROW; ++r) {
            y0[r] = fmaf(cf, wn0[r] - w0[r], wn0[r]);
            y1[r] = fmaf(cf, wn1[r] - w1[r], wn1[r]);
            w0[r] = wn0[r]; w1[r] = wn1[r];
        }
        t = tn;

        // Early exit: whole warp's w frozen (<5e-7) for one iteration.
        // Under restarted (monotone) convergence remaining drift ~ 10x the
        // threshold => ~5e-6 abs, 200x inside the 1e-3 budget.
        if (__all_sync(FULL, mxchg < 5e-7f)) break;
    }

    #pragma unroll
    for (int r = 0; r < NROW; ++r)
        reinterpret_cast<float2*>(out + (size_t)(row0 + r) * 64)[lane] =
            make_float2(w0[r], w1[r]);
}

// ---------- launch ----------
extern "C" void kernel_launch(void* const* d_in, const int* in_sizes, int n_in,
                              void* d_out, int out_size) {
    const float* x     = (const float*)d_in[0];
    const float* W1    = (const float*)d_in[1];
    const float* b1    = (const float*)d_in[2];
    const float* W2    = (const float*)d_in[3];
    const float* b2    = (const float*)d_in[4];
    const float* W3    = (const float*)d_in[5];
    const float* b3    = (const float*)d_in[6];
    const float* sigma = (const float*)d_in[7];
    const float* gamma = (const float*)d_in[8];
    float* out = (float*)d_out;

    int B = in_sizes[0] / 128;  // x is [B, 128]

    int mlp_blocks = (B + 7) / 8;
    prep_kernel<<<mlp_blocks + 1, 256>>>(x, W1, b1, W2, b2, W3, b3, sigma,
                                         out + (size_t)B * 64, B);
    int warps = (B + NROW - 1) / NROW;
    fista_kernel<<<(warps + 3) / 4, 128>>>(sigma, gamma, out, B);
}